// round 2
// baseline (speedup 1.0000x reference)
#include <cuda_runtime.h>
#include <cuda_fp16.h>
#include <cstdint>

// N=2048, F_IN=128, F_OUT=64
//   H = X@W + b
//   out[j,f] = sum_k mf[j,k]*H[k,f]* (sum_i A[j,i]*H[i,f]*mh[i,k])
// Per f: G_f = A . diag(h_f) . mh  (2048^3 fp16 mma.sync GEMM, fp32 accum in
// registers), k contracted immediately in the epilogue (G never materialized).
// tcgen05 is NOT available in this toolchain target (sm_103 non-a) -> use
// family-portable mma.sync.m16n8k16 + ldmatrix + cp.async.

#define NN   2048
#define FIN  128
#define FOUT 64

#define JT 128     // j rows per CTA
#define KT 64      // k cols per CTA
#define FB 4       // f per CTA
#define IC 64      // i (reduction) chunk
#define NCHUNK (NN / IC)

// ---- smem layout (bytes) ----
// A:  [2 buf][128 j][64 i fp16] rows 128B, XOR16-swizzled          = 32768
// MH: [2 buf][64 i][68 fp32] (stride 68 floats = 272B, 16B-aligned) = 34816
// B:  [4 f][64 n][64 i fp16] rows 128B, XOR16-swizzled              = 32768
// H:  [2 buf][64 i][4 f fp32]                                       = 2048
#define SM_A    0
#define SM_MH   32768
#define MH_ST   68
#define SM_B    67584
#define SM_H    100352
#define SMEM_TOTAL 102400

__device__ float  g_H[NN * FOUT];         // H = X@W + b (fp32)
__device__ __half g_Ah[(size_t)NN * NN];  // adjacency fp16

// ---------------- helpers ----------------
__device__ __forceinline__ uint32_t smem_to_u32(const void* p) {
    uint32_t a;
    asm("{ .reg .u64 t; cvta.to.shared.u64 t, %1; cvt.u32.u64 %0, t; }"
        : "=r"(a) : "l"(p));
    return a;
}
__device__ __forceinline__ void cp16(uint32_t dst, const void* src) {
    asm volatile("cp.async.cg.shared.global [%0], [%1], 16;" :: "r"(dst), "l"(src));
}
__device__ __forceinline__ void cp_commit() {
    asm volatile("cp.async.commit_group;" ::: "memory");
}
__device__ __forceinline__ uint32_t lds32(uint32_t addr) {
    uint32_t v;
    asm volatile("ld.shared.b32 %0, [%1];" : "=r"(v) : "r"(addr));
    return v;
}
__device__ __forceinline__ void ldm4(uint32_t* r, uint32_t addr) {
    asm volatile("ldmatrix.sync.aligned.m8n8.x4.shared.b16 {%0,%1,%2,%3}, [%4];"
                 : "=r"(r[0]), "=r"(r[1]), "=r"(r[2]), "=r"(r[3]) : "r"(addr));
}
__device__ __forceinline__ void mma16816(float* c, const uint32_t* a,
                                         uint32_t b0, uint32_t b1) {
    asm volatile(
        "mma.sync.aligned.m16n8k16.row.col.f32.f16.f16.f32 "
        "{%0,%1,%2,%3}, {%4,%5,%6,%7}, {%8,%9}, {%0,%1,%2,%3};"
        : "+f"(c[0]), "+f"(c[1]), "+f"(c[2]), "+f"(c[3])
        : "r"(a[0]), "r"(a[1]), "r"(a[2]), "r"(a[3]), "r"(b0), "r"(b1));
}

// ---------------- prep kernels ----------------
__global__ void prep_H(const float* __restrict__ X, const float* __restrict__ W,
                       const float* __restrict__ bias) {
    int id = blockIdx.x * blockDim.x + threadIdx.x;  // 131072
    int i = id >> 6, f = id & 63;
    float s = 0.f;
#pragma unroll 8
    for (int c = 0; c < FIN; c++) s += X[i * FIN + c] * W[c * FOUT + f];
    g_H[id] = s + bias[f];
}

__global__ void prep_A(const float* __restrict__ A) {
    size_t id = (size_t)blockIdx.x * blockDim.x + threadIdx.x;  // 2097152 pairs
    float2 v = ((const float2*)A)[id];
    ((__half2*)g_Ah)[id] = __floats2half2_rn(v.x, v.y);
}

__global__ void zero_out(float* __restrict__ out) {
    out[blockIdx.x * blockDim.x + threadIdx.x] = 0.f;
}

// ---------------- main kernel ----------------
// grid (16 jt, 32 kt, 16 f-quads), 256 threads (8 warps: 4 along j x 2 along k)
__global__ void __launch_bounds__(256, 1)
interaction_main(const float* __restrict__ mf, const float* __restrict__ mh,
                 float* __restrict__ out) {
    extern __shared__ char smem[];
    const uint32_t sb = smem_to_u32(smem);
    const int tid = threadIdx.x;
    const int lane = tid & 31, wid = tid >> 5;
    const int g = lane >> 2, tg = lane & 3;
    const int jbase = blockIdx.x * JT;
    const int kb0 = blockIdx.y * KT;
    const int f0 = blockIdx.z * FB;
    const int jbw = (wid & 3) * 32;    // warp j block
    const int kbw = (wid >> 2) * 32;   // warp k block

    float acc[FB][2][4][4];
#pragma unroll
    for (int f = 0; f < FB; f++)
#pragma unroll
        for (int mt = 0; mt < 2; mt++)
#pragma unroll
            for (int nt = 0; nt < 4; nt++)
#pragma unroll
                for (int c = 0; c < 4; c++) acc[f][mt][nt][c] = 0.f;

    // ---- prologue: issue chunk 0 ----
    {
        const int ibase = 0;
#pragma unroll
        for (int o = 0; o < 4; o++) {
            int idx = tid + o * 256, j = idx >> 3, cc = idx & 7;
            cp16(sb + SM_A + j * 128 + ((cc * 16) ^ ((j & 7) * 16)),
                 g_Ah + (size_t)(jbase + j) * NN + ibase + cc * 8);
        }
#pragma unroll
        for (int o = 0; o < 4; o++) {
            int idx = tid + o * 256, i = idx >> 4, cc = idx & 15;
            cp16(sb + SM_MH + i * (MH_ST * 4) + cc * 16,
                 mh + (size_t)(ibase + i) * NN + kb0 + cc * 4);
        }
        if (tid < 64)
            cp16(sb + SM_H + tid * 16, g_H + (ibase + tid) * FOUT + f0);
        cp_commit();
    }

    for (int c = 0; c < NCHUNK; c++) {
        const int buf = c & 1;
        // issue next chunk into other buffer
        if (c + 1 < NCHUNK) {
            const int nb = (c + 1) & 1;
            const int ibase = (c + 1) * IC;
#pragma unroll
            for (int o = 0; o < 4; o++) {
                int idx = tid + o * 256, j = idx >> 3, cc = idx & 7;
                cp16(sb + SM_A + nb * 16384 + j * 128 + ((cc * 16) ^ ((j & 7) * 16)),
                     g_Ah + (size_t)(jbase + j) * NN + ibase + cc * 8);
            }
#pragma unroll
            for (int o = 0; o < 4; o++) {
                int idx = tid + o * 256, i = idx >> 4, cc = idx & 15;
                cp16(sb + SM_MH + nb * 17408 + i * (MH_ST * 4) + cc * 16,
                     mh + (size_t)(ibase + i) * NN + kb0 + cc * 4);
            }
            if (tid < 64)
                cp16(sb + SM_H + nb * 1024 + tid * 16,
                     g_H + (ibase + tid) * FOUT + f0);
            cp_commit();
            asm volatile("cp.async.wait_group 1;" ::: "memory");
        } else {
            asm volatile("cp.async.wait_group 0;" ::: "memory");
        }
        __syncthreads();  // chunk c data visible; B buffer free

        // ---- build B_f[n][i] = fp16(mh[i, kb0+n] * H[i, f0+f]) ----
        {
            const int f = tid >> 6, l = tid & 63;
            const float* mhc = (const float*)(smem + SM_MH + buf * 17408);
            const float* hc  = (const float*)(smem + SM_H + buf * 1024);
            char* Bf = smem + SM_B + f * 8192;
#pragma unroll
            for (int ib = 0; ib < 4; ib++)
#pragma unroll
                for (int nb2 = 0; nb2 < 8; nb2++) {
                    int n = (l & 7) + nb2 * 8;
                    int i = 2 * (l >> 3) + 16 * ib;
                    float h0v = hc[i * 4 + f], h1v = hc[(i + 1) * 4 + f];
                    float m0v = mhc[i * MH_ST + n], m1v = mhc[(i + 1) * MH_ST + n];
                    __half2 p = __floats2half2_rn(m0v * h0v, m1v * h1v);
                    *(uint32_t*)(Bf + n * 128 + ((i * 2) ^ ((n & 7) * 16))) =
                        *(uint32_t*)&p;
                }
        }
        __syncthreads();  // B visible

        // ---- mma over 4 k16 steps ----
        const uint32_t abase = sb + SM_A + buf * 16384;
#pragma unroll
        for (int ks = 0; ks < 4; ks++) {
            uint32_t a[2][4];
#pragma unroll
            for (int mt = 0; mt < 2; mt++) {
                int jr = jbw + mt * 16 + (lane & 15);
                ldm4(a[mt], abase + jr * 128 +
                              ((((lane >> 4) * 16) + ks * 32) ^ ((jr & 7) * 16)));
            }
#pragma unroll
            for (int f = 0; f < FB; f++) {
#pragma unroll
                for (int nt = 0; nt < 4; nt++) {
                    int n = kbw + nt * 8 + g;
                    uint32_t baddr = sb + SM_B + f * 8192 + n * 128 +
                                     (((ks * 32) + tg * 4) ^ ((n & 7) * 16));
                    uint32_t b0 = lds32(baddr);
                    uint32_t b1 = lds32(baddr ^ 16);
                    mma16816(acc[f][0][nt], a[0], b0, b1);
                    mma16816(acc[f][1][nt], a[1], b0, b1);
                }
            }
        }
        __syncthreads();  // A/mh/B buffers free for next iteration
    }

    // ---- epilogue: out[j,f] += sum_k acc * mf[j,k] * H[k,f] ----
    float* mfs = (float*)(smem + SM_MH);  // [128][MH_ST]
#pragma unroll
    for (int o = 0; o < 32; o++) {
        int idx = tid + o * 256, r = idx >> 6, cc = idx & 63;
        mfs[r * MH_ST + cc] = mf[(size_t)(jbase + r) * NN + kb0 + cc];
    }
    float* Hk = (float*)(smem + SM_H);  // [64][4]
    {
        int kk = tid >> 2, ff = tid & 3;
        Hk[kk * 4 + ff] = g_H[(kb0 + kk) * FOUT + f0 + ff];
    }
    __syncthreads();

#pragma unroll
    for (int f = 0; f < FB; f++)
#pragma unroll
        for (int mt = 0; mt < 2; mt++)
#pragma unroll
            for (int h2 = 0; h2 < 2; h2++) {
                int j = jbw + mt * 16 + g + 8 * h2;
                float s = 0.f;
#pragma unroll
                for (int nt = 0; nt < 4; nt++)
#pragma unroll
                    for (int e = 0; e < 2; e++) {
                        int k = kbw + nt * 8 + tg * 2 + e;
                        s += acc[f][mt][nt][h2 * 2 + e] * mfs[j * MH_ST + k] *
                             Hk[k * 4 + f];
                    }
                s += __shfl_xor_sync(0xffffffffu, s, 1);
                s += __shfl_xor_sync(0xffffffffu, s, 2);
                if (tg == 0)
                    atomicAdd(&out[(size_t)(jbase + j) * FOUT + f0 + f], s);
            }
}

// ---------------- launch ----------------
extern "C" void kernel_launch(void* const* d_in, const int* in_sizes, int n_in,
                              void* d_out, int out_size) {
    const float* X  = (const float*)d_in[0];  // node_features [2048,128]
    const float* A  = (const float*)d_in[1];  // adjacency     [2048,2048]
    const float* mf = (const float*)d_in[2];  // mask_father   [2048,2048]
    const float* mh = (const float*)d_in[3];  // mask_hadamard [2048,2048]
    const float* W  = (const float*)d_in[4];  // weight        [128,64]
    const float* b  = (const float*)d_in[5];  // bias          [64]
    float* out = (float*)d_out;               // [2048,64] fp32

    cudaFuncSetAttribute(interaction_main,
                         cudaFuncAttributeMaxDynamicSharedMemorySize, SMEM_TOTAL);

    prep_H<<<256, 512>>>(X, W, b);
    prep_A<<<4096, 512>>>(A);
    zero_out<<<256, 512>>>(out);
    interaction_main<<<dim3(16, 32, 16), 256, SMEM_TOTAL>>>(mf, mh, out);
}

// round 4
// speedup vs baseline: 1.2596x; 1.2596x over previous
#include <cuda_runtime.h>
#include <cuda_fp16.h>
#include <cstdint>

// N=2048, F_IN=128, F_OUT=64
//   H = X@W + b
//   out[j,f] = sum_k mf[j,k]*H[k,f]* (sum_i A[j,i]*H[i,f]*mh[i,k])
// Per f: G_f = A . diag(h_f) . mh  (fp16 mma.sync, fp32 accum), k contracted
// immediately in the epilogue. B fragments built IN REGISTERS from fp32 mh
// smem tile (single rounding mh*h -> fp16), no B smem tile, 3-stage cp.async.
// R4 fix: epilogue Hk buffer moved past the mf tile (R3 had them overlapping).

#define NN   2048
#define FIN  128
#define FOUT 64

#define JT 128
#define KT 64
#define FB 4
#define IC 64
#define NCHUNK (NN / IC)

// ---- smem: 3 stages of {A fp16 swizzled, mh fp32, H fp32} ----
#define ST_A   0        // [128 j][64 i] fp16, 128B rows, XOR16 swizzle = 16384
#define ST_MH  16384    // [64 i][68 fp32]                              = 17408
#define ST_H   33792    // [64 i][4 f fp32]                             = 1024
#define STAGE  34816
#define MH_ST  68
#define MF_ST  76       // epilogue mf stride (2-way max conflicts)
#define EP_HK  (128 * MF_ST * 4)   // 38912: Hk AFTER the mf tile
#define SMEM_TOTAL (3 * STAGE)     // 104448

__device__ float  g_H[NN * FOUT];
__device__ __half g_Ah[(size_t)NN * NN];

// ---------------- helpers ----------------
__device__ __forceinline__ uint32_t smem_to_u32(const void* p) {
    uint32_t a;
    asm("{ .reg .u64 t; cvta.to.shared.u64 t, %1; cvt.u32.u64 %0, t; }"
        : "=r"(a) : "l"(p));
    return a;
}
__device__ __forceinline__ void cp16(uint32_t dst, const void* src) {
    asm volatile("cp.async.cg.shared.global [%0], [%1], 16;" :: "r"(dst), "l"(src));
}
__device__ __forceinline__ void cp_commit() {
    asm volatile("cp.async.commit_group;" ::: "memory");
}
__device__ __forceinline__ void ldm4(uint32_t* r, uint32_t addr) {
    asm volatile("ldmatrix.sync.aligned.m8n8.x4.shared.b16 {%0,%1,%2,%3}, [%4];"
                 : "=r"(r[0]), "=r"(r[1]), "=r"(r[2]), "=r"(r[3]) : "r"(addr));
}
__device__ __forceinline__ void mma16816(float* c, const uint32_t* a,
                                         uint32_t b0, uint32_t b1) {
    asm volatile(
        "mma.sync.aligned.m16n8k16.row.col.f32.f16.f16.f32 "
        "{%0,%1,%2,%3}, {%4,%5,%6,%7}, {%8,%9}, {%0,%1,%2,%3};"
        : "+f"(c[0]), "+f"(c[1]), "+f"(c[2]), "+f"(c[3])
        : "r"(a[0]), "r"(a[1]), "r"(a[2]), "r"(a[3]), "r"(b0), "r"(b1));
}

// ---------------- prep ----------------
__global__ void prep_H(const float* __restrict__ X, const float* __restrict__ W,
                       const float* __restrict__ bias) {
    int id = blockIdx.x * blockDim.x + threadIdx.x;
    int i = id >> 6, f = id & 63;
    float s = 0.f;
#pragma unroll 8
    for (int c = 0; c < FIN; c++) s += X[i * FIN + c] * W[c * FOUT + f];
    g_H[id] = s + bias[f];
}
__global__ void prep_A(const float* __restrict__ A) {
    size_t id = (size_t)blockIdx.x * blockDim.x + threadIdx.x;
    float2 v = ((const float2*)A)[id];
    ((__half2*)g_Ah)[id] = __floats2half2_rn(v.x, v.y);
}
__global__ void zero_out(float* __restrict__ out) {
    out[blockIdx.x * blockDim.x + threadIdx.x] = 0.f;
}

// ---------------- main ----------------
// grid (16 jt, 32 kt, 16 fq), 256 threads = 8 warps laid out 2 (j) x 4 (k).
__global__ void __launch_bounds__(256, 1)
interaction_main(const float* __restrict__ mf, const float* __restrict__ mh,
                 float* __restrict__ out) {
    extern __shared__ char smem[];
    const uint32_t sb = smem_to_u32(smem);
    const int tid = threadIdx.x;
    const int lane = tid & 31, wid = tid >> 5;
    const int g = lane >> 2, tg = lane & 3;
    const int jbase = blockIdx.x * JT;
    const int kb0 = blockIdx.y * KT;
    const int f0 = blockIdx.z * FB;
    const int jbw = (wid & 1) * 64;    // warp j block (mt covers 4x16)
    const int kbw = (wid >> 1) * 16;   // warp k block (nt covers 2x8)

    float acc[FB][4][2][4];
#pragma unroll
    for (int f = 0; f < FB; f++)
#pragma unroll
        for (int mt = 0; mt < 4; mt++)
#pragma unroll
            for (int nt = 0; nt < 2; nt++)
#pragma unroll
                for (int c = 0; c < 4; c++) acc[f][mt][nt][c] = 0.f;

    // ---- chunk loader ----
    auto issue = [&](int c, int st) {
        const uint32_t base = sb + st * STAGE;
        const int ibase = c * IC;
#pragma unroll
        for (int o = 0; o < 4; o++) {
            int idx = tid + o * 256, j = idx >> 3, cc = idx & 7;
            cp16(base + ST_A + j * 128 + ((cc * 16) ^ ((j & 7) * 16)),
                 g_Ah + (size_t)(jbase + j) * NN + ibase + cc * 8);
        }
#pragma unroll
        for (int o = 0; o < 4; o++) {
            int idx = tid + o * 256, i = idx >> 4, cc = idx & 15;
            cp16(base + ST_MH + i * (MH_ST * 4) + cc * 16,
                 mh + (size_t)(ibase + i) * NN + kb0 + cc * 4);
        }
        if (tid < 64)
            cp16(base + ST_H + tid * 16, g_H + (ibase + tid) * FOUT + f0);
        cp_commit();
    };

    issue(0, 0);
    issue(1, 1);

    for (int c = 0; c < NCHUNK; c++) {
        const int st = c % 3;
        if (c + 2 < NCHUNK) {
            issue(c + 2, (c + 2) % 3);
            asm volatile("cp.async.wait_group 2;" ::: "memory");
        } else if (c + 1 < NCHUNK) {
            asm volatile("cp.async.wait_group 1;" ::: "memory");
        } else {
            asm volatile("cp.async.wait_group 0;" ::: "memory");
        }
        __syncthreads();  // chunk c visible to all warps

        const uint32_t abase = sb + st * STAGE + ST_A;
        const float* mhc = (const float*)(smem + st * STAGE + ST_MH);
        const float* hc  = (const float*)(smem + st * STAGE + ST_H);

#pragma unroll
        for (int ks = 0; ks < 4; ks++) {
            // A fragments: 4 m16 tiles
            uint32_t a[4][4];
#pragma unroll
            for (int mt = 0; mt < 4; mt++) {
                int jr = jbw + mt * 16 + (lane & 15);
                ldm4(a[mt], abase + jr * 128 +
                               ((((lane >> 4) * 16) + ks * 32) ^ ((jr & 7) * 16)));
            }
            // mh values for this lane's B-fragment positions
            const int i0 = ks * 16 + tg * 2;
            float m[2][4];
#pragma unroll
            for (int nt = 0; nt < 2; nt++) {
                int n = kbw + nt * 8 + g;
                m[nt][0] = mhc[i0 * MH_ST + n];
                m[nt][1] = mhc[(i0 + 1) * MH_ST + n];
                m[nt][2] = mhc[(i0 + 8) * MH_ST + n];
                m[nt][3] = mhc[(i0 + 9) * MH_ST + n];
            }
#pragma unroll
            for (int f = 0; f < FB; f++) {
                const float h0 = hc[i0 * 4 + f];
                const float h1 = hc[(i0 + 1) * 4 + f];
                const float h2 = hc[(i0 + 8) * 4 + f];
                const float h3 = hc[(i0 + 9) * 4 + f];
#pragma unroll
                for (int nt = 0; nt < 2; nt++) {
                    __half2 b0h = __floats2half2_rn(m[nt][0] * h0, m[nt][1] * h1);
                    __half2 b1h = __floats2half2_rn(m[nt][2] * h2, m[nt][3] * h3);
                    uint32_t b0 = *(uint32_t*)&b0h, b1 = *(uint32_t*)&b1h;
#pragma unroll
                    for (int mt = 0; mt < 4; mt++)
                        mma16816(acc[f][mt][nt], a[mt], b0, b1);
                }
            }
        }
        __syncthreads();  // stage st free for reuse
    }

    // ---- epilogue: out[j,f] += sum_k acc * mf[j,k] * H[k,f] ----
    float* mfs = (float*)smem;                     // [128][MF_ST] = 38912 B
    float* Hk  = (float*)(smem + EP_HK);           // [64][4] at 38912 (no overlap)
#pragma unroll
    for (int o = 0; o < 32; o++) {
        int idx = tid + o * 256, r = idx >> 6, cc = idx & 63;
        mfs[r * MF_ST + cc] = mf[(size_t)(jbase + r) * NN + kb0 + cc];
    }
    {
        int kk = tid >> 2, ff = tid & 3;
        Hk[kk * 4 + ff] = g_H[(kb0 + kk) * FOUT + f0 + ff];
    }
    __syncthreads();

#pragma unroll
    for (int f = 0; f < FB; f++)
#pragma unroll
        for (int mt = 0; mt < 4; mt++)
#pragma unroll
            for (int h2 = 0; h2 < 2; h2++) {
                int j = jbw + mt * 16 + g + 8 * h2;
                float s = 0.f;
#pragma unroll
                for (int nt = 0; nt < 2; nt++)
#pragma unroll
                    for (int e = 0; e < 2; e++) {
                        int k = kbw + nt * 8 + tg * 2 + e;
                        s += acc[f][mt][nt][h2 * 2 + e] * mfs[j * MF_ST + k] *
                             Hk[k * 4 + f];
                    }
                s += __shfl_xor_sync(0xffffffffu, s, 1);
                s += __shfl_xor_sync(0xffffffffu, s, 2);
                if (tg == 0)
                    atomicAdd(&out[(size_t)(jbase + j) * FOUT + f0 + f], s);
            }
}

// ---------------- launch ----------------
extern "C" void kernel_launch(void* const* d_in, const int* in_sizes, int n_in,
                              void* d_out, int out_size) {
    const float* X  = (const float*)d_in[0];
    const float* A  = (const float*)d_in[1];
    const float* mf = (const float*)d_in[2];
    const float* mh = (const float*)d_in[3];
    const float* W  = (const float*)d_in[4];
    const float* b  = (const float*)d_in[5];
    float* out = (float*)d_out;

    cudaFuncSetAttribute(interaction_main,
                         cudaFuncAttributeMaxDynamicSharedMemorySize, SMEM_TOTAL);

    prep_H<<<256, 512>>>(X, W, b);
    prep_A<<<4096, 512>>>(A);
    zero_out<<<256, 512>>>(out);
    interaction_main<<<dim3(16, 32, 16), 256, SMEM_TOTAL>>>(mf, mh, out);
}

// round 5
// speedup vs baseline: 1.5602x; 1.2386x over previous
#include <cuda_runtime.h>
#include <cuda_fp16.h>
#include <cstdint>

// N=2048, F_IN=128, F_OUT=64
//   H = X@W + b
//   out[j,f] = sum_k mf[j,k]*H[k,f]* (sum_i A[j,i]*H[i,f]*mh[i,k])
// Per f: G_f = A . diag(h_f) . mh  (fp16 mma.sync, fp32 accum), k contracted
// immediately in the epilogue.
// R5: mh pre-transposed to fp16 [k][i] -> B frags via ldmatrix.x4, H folded in
// with HMUL2 on packed frags. Non-mma issue stream cut ~2.5x vs R4.

#define NN   2048
#define FIN  128
#define FOUT 64

#define JT 128
#define KT 64
#define FB 4
#define IC 64
#define NCHUNK (NN / IC)

// ---- smem: 3 stages of {A fp16 swizzled, mhT fp16 swizzled, Hh fp16} ----
#define ST_A   0        // [128 j][64 i] fp16, 128B rows, XOR16 swizzle = 16384
#define ST_MH  16384    // [64 k][64 i] fp16, 128B rows, XOR16 swizzle = 8192
#define ST_H   24576    // [4 f][64 i] fp16 (128B rows, linear)        = 512
#define STAGE  25088
#define MF_ST  76       // epilogue mf stride (fp32 words)
#define EP_HK  (128 * MF_ST * 4)       // 38912
#define SMEM_TOTAL (3 * STAGE)         // 75264

__device__ float  g_H[NN * FOUT];          // fp32 H for epilogue
__device__ __half g_HhT[FOUT * NN];        // fp16 H transposed [f][i]
__device__ __half g_Ah[(size_t)NN * NN];   // adjacency fp16 [j][i]
__device__ __half g_mhT[(size_t)NN * NN];  // mask_hadamard fp16 transposed [k][i]

// ---------------- helpers ----------------
__device__ __forceinline__ uint32_t smem_to_u32(const void* p) {
    uint32_t a;
    asm("{ .reg .u64 t; cvta.to.shared.u64 t, %1; cvt.u32.u64 %0, t; }"
        : "=r"(a) : "l"(p));
    return a;
}
__device__ __forceinline__ void cp16(uint32_t dst, const void* src) {
    asm volatile("cp.async.cg.shared.global [%0], [%1], 16;" :: "r"(dst), "l"(src));
}
__device__ __forceinline__ void cp_commit() {
    asm volatile("cp.async.commit_group;" ::: "memory");
}
__device__ __forceinline__ uint32_t lds32(uint32_t addr) {
    uint32_t v;
    asm volatile("ld.shared.b32 %0, [%1];" : "=r"(v) : "r"(addr));
    return v;
}
__device__ __forceinline__ void ldm4(uint32_t* r, uint32_t addr) {
    asm volatile("ldmatrix.sync.aligned.m8n8.x4.shared.b16 {%0,%1,%2,%3}, [%4];"
                 : "=r"(r[0]), "=r"(r[1]), "=r"(r[2]), "=r"(r[3]) : "r"(addr));
}
__device__ __forceinline__ uint32_t hmul2u(uint32_t a, uint32_t b) {
    __half2 r = __hmul2(*(__half2*)&a, *(__half2*)&b);
    return *(uint32_t*)&r;
}
__device__ __forceinline__ void mma16816(float* c, const uint32_t* a,
                                         uint32_t b0, uint32_t b1) {
    asm volatile(
        "mma.sync.aligned.m16n8k16.row.col.f32.f16.f16.f32 "
        "{%0,%1,%2,%3}, {%4,%5,%6,%7}, {%8,%9}, {%0,%1,%2,%3};"
        : "+f"(c[0]), "+f"(c[1]), "+f"(c[2]), "+f"(c[3])
        : "r"(a[0]), "r"(a[1]), "r"(a[2]), "r"(a[3]), "r"(b0), "r"(b1));
}

// ---------------- prep ----------------
__global__ void prep_H(const float* __restrict__ X, const float* __restrict__ W,
                       const float* __restrict__ bias) {
    int id = blockIdx.x * blockDim.x + threadIdx.x;  // 131072
    int i = id >> 6, f = id & 63;
    float s = 0.f;
#pragma unroll 8
    for (int c = 0; c < FIN; c++) s += X[i * FIN + c] * W[c * FOUT + f];
    s += bias[f];
    g_H[id] = s;
    g_HhT[f * NN + i] = __float2half_rn(s);
}
__global__ void prep_A(const float* __restrict__ A) {
    size_t id = (size_t)blockIdx.x * blockDim.x + threadIdx.x;
    float2 v = ((const float2*)A)[id];
    ((__half2*)g_Ah)[id] = __floats2half2_rn(v.x, v.y);
}
// tiled transpose + fp16 convert: g_mhT[k][i] = fp16(mh[i][k])
__global__ void prep_mhT(const float* __restrict__ mh) {
    __shared__ float t[32][33];
    const int bx = blockIdx.x * 32, by = blockIdx.y * 32;  // bx: k, by: i
    const int tx = threadIdx.x & 31, ty = threadIdx.x >> 5;
#pragma unroll
    for (int y = ty; y < 32; y += 8)
        t[y][tx] = mh[(size_t)(by + y) * NN + bx + tx];
    __syncthreads();
#pragma unroll
    for (int o = 0; o < 2; o++) {
        int idx = threadIdx.x + o * 256;       // 0..511
        int kr = idx >> 4, ip = idx & 15;      // k row, i half2 index
        __half2 v = __floats2half2_rn(t[ip * 2][kr], t[ip * 2 + 1][kr]);
        *(__half2*)&g_mhT[(size_t)(bx + kr) * NN + by + ip * 2] = v;
    }
}
__global__ void zero_out(float* __restrict__ out) {
    out[blockIdx.x * blockDim.x + threadIdx.x] = 0.f;
}

// ---------------- main ----------------
// grid (16 jt, 32 kt, 16 fq), 256 threads = 8 warps laid out 2 (j) x 4 (k).
__global__ void __launch_bounds__(256, 1)
interaction_main(const float* __restrict__ mf, float* __restrict__ out) {
    extern __shared__ char smem[];
    const uint32_t sb = smem_to_u32(smem);
    const int tid = threadIdx.x;
    const int lane = tid & 31, wid = tid >> 5;
    const int g = lane >> 2, tg = lane & 3;
    const int jbase = blockIdx.x * JT;
    const int kb0 = blockIdx.y * KT;
    const int f0 = blockIdx.z * FB;
    const int jbw = (wid & 1) * 64;    // warp j block (4 x m16)
    const int kbw = (wid >> 1) * 16;   // warp k block (2 x n8)

    float acc[FB][4][2][4];
#pragma unroll
    for (int f = 0; f < FB; f++)
#pragma unroll
        for (int mt = 0; mt < 4; mt++)
#pragma unroll
            for (int nt = 0; nt < 2; nt++)
#pragma unroll
                for (int c = 0; c < 4; c++) acc[f][mt][nt][c] = 0.f;

    // per-lane ldmatrix row addresses (offsets within a stage)
    // A: jr = jbw + mt*16 + (lane&15), col halves select by lane>>4
    // B: tile id = lane>>3: bit0 -> i-half, bit1 -> n8 tile
    const int btl = lane >> 3, brr = lane & 7;
    const int bn = kbw + ((btl >> 1) & 1) * 8 + brr;
    const uint32_t bcol0 = (uint32_t)((btl & 1) * 16);

    // ---- chunk loader ----
    auto issue = [&](int c, int st) {
        const uint32_t base = sb + st * STAGE;
        const int ibase = c * IC;
#pragma unroll
        for (int o = 0; o < 4; o++) {
            int idx = tid + o * 256, j = idx >> 3, cc = idx & 7;
            cp16(base + ST_A + j * 128 + ((cc * 16) ^ ((j & 7) * 16)),
                 g_Ah + (size_t)(jbase + j) * NN + ibase + cc * 8);
        }
#pragma unroll
        for (int o = 0; o < 2; o++) {
            int idx = tid + o * 256, n = idx >> 3, cc = idx & 7;
            cp16(base + ST_MH + n * 128 + ((cc * 16) ^ ((n & 7) * 16)),
                 g_mhT + (size_t)(kb0 + n) * NN + ibase + cc * 8);
        }
        if (tid < 32) {
            int f = tid >> 3, cc = tid & 7;
            cp16(base + ST_H + f * 128 + cc * 16,
                 g_HhT + (size_t)(f0 + f) * NN + ibase + cc * 8);
        }
        cp_commit();
    };

    issue(0, 0);
    issue(1, 1);

    for (int c = 0; c < NCHUNK; c++) {
        const int st = c % 3;
        if (c + 2 < NCHUNK) {
            issue(c + 2, (c + 2) % 3);
            asm volatile("cp.async.wait_group 2;" ::: "memory");
        } else if (c + 1 < NCHUNK) {
            asm volatile("cp.async.wait_group 1;" ::: "memory");
        } else {
            asm volatile("cp.async.wait_group 0;" ::: "memory");
        }
        __syncthreads();

        const uint32_t abase = sb + st * STAGE + ST_A;
        const uint32_t mbase = sb + st * STAGE + ST_MH;
        const uint32_t hbase = sb + st * STAGE + ST_H;

#pragma unroll
        for (int ks = 0; ks < 4; ks++) {
            // A fragments: 4 m16 tiles (pure adjacency, fp16)
            uint32_t a[4][4];
#pragma unroll
            for (int mt = 0; mt < 4; mt++) {
                int jr = jbw + mt * 16 + (lane & 15);
                ldm4(a[mt], abase + jr * 128 +
                               ((((lane >> 4) * 16) + ks * 32) ^ ((jr & 7) * 16)));
            }
            // mh fragments: one ldmatrix.x4 covers both n8 tiles, k16
            uint32_t bfr[4];
            ldm4(bfr, mbase + bn * 128 + ((ks * 32 + bcol0) ^ ((bn & 7) * 16)));

#pragma unroll
            for (int f = 0; f < FB; f++) {
                // h half2 pairs at i = ks*16 + tg*2 (+1) and +8 (+9)
                uint32_t hA = lds32(hbase + f * 128 + ks * 32 + tg * 4);
                uint32_t hB = lds32(hbase + f * 128 + ks * 32 + tg * 4 + 16);
                uint32_t b00 = hmul2u(bfr[0], hA);
                uint32_t b01 = hmul2u(bfr[1], hB);
                uint32_t b10 = hmul2u(bfr[2], hA);
                uint32_t b11 = hmul2u(bfr[3], hB);
#pragma unroll
                for (int mt = 0; mt < 4; mt++) {
                    mma16816(acc[f][mt][0], a[mt], b00, b01);
                    mma16816(acc[f][mt][1], a[mt], b10, b11);
                }
            }
        }
        __syncthreads();
    }

    // ---- epilogue: out[j,f] += sum_k acc * mf[j,k] * H[k,f] ----
    float* mfs = (float*)smem;               // [128][MF_ST] fp32 = 38912 B
    float* Hk  = (float*)(smem + EP_HK);     // [64][4] fp32
#pragma unroll
    for (int o = 0; o < 32; o++) {
        int idx = tid + o * 256, r = idx >> 6, cc = idx & 63;
        mfs[r * MF_ST + cc] = mf[(size_t)(jbase + r) * NN + kb0 + cc];
    }
    {
        int kk = tid >> 2, ff = tid & 3;
        Hk[kk * 4 + ff] = g_H[(kb0 + kk) * FOUT + f0 + ff];
    }
    __syncthreads();

#pragma unroll
    for (int f = 0; f < FB; f++)
#pragma unroll
        for (int mt = 0; mt < 4; mt++)
#pragma unroll
            for (int h2 = 0; h2 < 2; h2++) {
                int j = jbw + mt * 16 + g + 8 * h2;
                float s = 0.f;
#pragma unroll
                for (int nt = 0; nt < 2; nt++)
#pragma unroll
                    for (int e = 0; e < 2; e++) {
                        int k = kbw + nt * 8 + tg * 2 + e;
                        s += acc[f][mt][nt][h2 * 2 + e] * mfs[j * MF_ST + k] *
                             Hk[k * 4 + f];
                    }
                s += __shfl_xor_sync(0xffffffffu, s, 1);
                s += __shfl_xor_sync(0xffffffffu, s, 2);
                if (tg == 0)
                    atomicAdd(&out[(size_t)(jbase + j) * FOUT + f0 + f], s);
            }
}

// ---------------- launch ----------------
extern "C" void kernel_launch(void* const* d_in, const int* in_sizes, int n_in,
                              void* d_out, int out_size) {
    const float* X  = (const float*)d_in[0];
    const float* A  = (const float*)d_in[1];
    const float* mf = (const float*)d_in[2];
    const float* mh = (const float*)d_in[3];
    const float* W  = (const float*)d_in[4];
    const float* b  = (const float*)d_in[5];
    float* out = (float*)d_out;

    cudaFuncSetAttribute(interaction_main,
                         cudaFuncAttributeMaxDynamicSharedMemorySize, SMEM_TOTAL);

    prep_H<<<256, 512>>>(X, W, b);
    prep_A<<<4096, 512>>>(A);
    prep_mhT<<<dim3(64, 64), 256>>>(mh);
    zero_out<<<256, 512>>>(out);
    interaction_main<<<dim3(16, 32, 16), 256, SMEM_TOTAL>>>(mf, out);
}